// round 1
// baseline (speedup 1.0000x reference)
#include <cuda_runtime.h>
#include <cuda_bf16.h>
#include <math.h>

#define N_LEVELS 4
#define F_PER_LEVEL 4
#define HASHMAP_SIZE 32768
#define HASH_MASK 32767u

// Level resolutions: floor(16 * 1.5^l) = 16, 24, 36, 54
// Dense if (res+1)^3 <= 32768: 17^3=4913 dense, 25^3=15625 dense, 37^3, 55^3 hashed
__device__ __constant__ int d_res[4] = {16, 24, 36, 54};

__global__ void __launch_bounds__(256)
hashmlp_kernel(const float* __restrict__ dirs,
               const float* __restrict__ grid,
               const float* __restrict__ gW1, const float* __restrict__ gb1,
               const float* __restrict__ gW2, const float* __restrict__ gb2,
               const float* __restrict__ gW3, const float* __restrict__ gb3,
               const float* __restrict__ gW4, const float* __restrict__ gb4,
               float* __restrict__ out, int n)
{
    // ---- stage MLP weights in shared memory (~5 KB) ----
    __shared__ float sW1[16 * 32];
    __shared__ float sb1[32];
    __shared__ float sW2[32 * 16];
    __shared__ float sb2[16];
    __shared__ float sW3[16 * 8];
    __shared__ float sb3[8];
    __shared__ float sW4[8 * 3];
    __shared__ float sb4[3];

    int tid = threadIdx.x;
    for (int i = tid; i < 16 * 32; i += blockDim.x) sW1[i] = gW1[i];
    for (int i = tid; i < 32;      i += blockDim.x) sb1[i] = gb1[i];
    for (int i = tid; i < 32 * 16; i += blockDim.x) sW2[i] = gW2[i];
    for (int i = tid; i < 16;      i += blockDim.x) sb2[i] = gb2[i];
    for (int i = tid; i < 16 * 8;  i += blockDim.x) sW3[i] = gW3[i];
    for (int i = tid; i < 8;       i += blockDim.x) sb3[i] = gb3[i];
    for (int i = tid; i < 8 * 3;   i += blockDim.x) sW4[i] = gW4[i];
    for (int i = tid; i < 3;       i += blockDim.x) sb4[i] = gb4[i];
    __syncthreads();

    int gid = blockIdx.x * blockDim.x + tid;
    if (gid >= n) return;

    float dx = dirs[gid * 3 + 0];
    float dy = dirs[gid * 3 + 1];
    float dz = dirs[gid * 3 + 2];

    float feats[16];

    #pragma unroll
    for (int l = 0; l < N_LEVELS; l++) {
        const int res = (l == 0) ? 16 : (l == 1) ? 24 : (l == 2) ? 36 : 54;
        const bool dense = (l < 2);

        float px = dx * (float)res;
        float py = dy * (float)res;
        float pz = dz * (float)res;
        float fx0 = floorf(px), fy0 = floorf(py), fz0 = floorf(pz);
        float fx = px - fx0, fy = py - fy0, fz = pz - fz0;
        int ix0 = (int)fx0, iy0 = (int)fy0, iz0 = (int)fz0;

        float wx[2] = {1.0f - fx, fx};
        float wy[2] = {1.0f - fy, fy};
        float wz[2] = {1.0f - fz, fz};

        float a0 = 0.f, a1 = 0.f, a2 = 0.f, a3 = 0.f;

        const float* gl = grid + (size_t)l * HASHMAP_SIZE * F_PER_LEVEL;

        #pragma unroll
        for (int c = 0; c < 8; c++) {
            int bx = (c >> 2) & 1, by = (c >> 1) & 1, bz = c & 1;
            int cx = min(max(ix0 + bx, 0), res);
            int cy = min(max(iy0 + by, 0), res);
            int cz = min(max(iz0 + bz, 0), res);
            int idx;
            if (dense) {
                idx = cx + (res + 1) * (cy + (res + 1) * cz);
            } else {
                unsigned int h = (unsigned int)cx
                               ^ ((unsigned int)cy * 2654435761u)
                               ^ ((unsigned int)cz * 805459861u);
                idx = (int)(h & HASH_MASK);
            }
            float w = wx[bx] * wy[by] * wz[bz];
            float4 v = __ldg((const float4*)(gl + (size_t)idx * 4));
            a0 = fmaf(w, v.x, a0);
            a1 = fmaf(w, v.y, a1);
            a2 = fmaf(w, v.z, a2);
            a3 = fmaf(w, v.w, a3);
        }
        feats[l * 4 + 0] = a0;
        feats[l * 4 + 1] = a1;
        feats[l * 4 + 2] = a2;
        feats[l * 4 + 3] = a3;
    }

    // ---- MLP: 16 -> 32 -> 16 -> 8 -> 3, leaky(0.2) + tanh ----
    float h1[32];
    #pragma unroll
    for (int j = 0; j < 32; j++) {
        float acc = sb1[j];
        #pragma unroll
        for (int i = 0; i < 16; i++) acc = fmaf(feats[i], sW1[i * 32 + j], acc);
        h1[j] = (acc > 0.f) ? acc : 0.2f * acc;
    }

    float h2[16];
    #pragma unroll
    for (int j = 0; j < 16; j++) {
        float acc = sb2[j];
        #pragma unroll
        for (int i = 0; i < 32; i++) acc = fmaf(h1[i], sW2[i * 16 + j], acc);
        h2[j] = (acc > 0.f) ? acc : 0.2f * acc;
    }

    float h3[8];
    #pragma unroll
    for (int j = 0; j < 8; j++) {
        float acc = sb3[j];
        #pragma unroll
        for (int i = 0; i < 16; i++) acc = fmaf(h2[i], sW3[i * 8 + j], acc);
        h3[j] = (acc > 0.f) ? acc : 0.2f * acc;
    }

    #pragma unroll
    for (int j = 0; j < 3; j++) {
        float acc = sb4[j];
        #pragma unroll
        for (int i = 0; i < 8; i++) acc = fmaf(h3[i], sW4[i * 3 + j], acc);
        out[gid * 3 + j] = tanhf(acc);
    }
}

extern "C" void kernel_launch(void* const* d_in, const int* in_sizes, int n_in,
                              void* d_out, int out_size) {
    const float* dirs = (const float*)d_in[0];
    const float* grid = (const float*)d_in[1];
    const float* W1 = (const float*)d_in[2];
    const float* b1 = (const float*)d_in[3];
    const float* W2 = (const float*)d_in[4];
    const float* b2 = (const float*)d_in[5];
    const float* W3 = (const float*)d_in[6];
    const float* b3 = (const float*)d_in[7];
    const float* W4 = (const float*)d_in[8];
    const float* b4 = (const float*)d_in[9];
    float* out = (float*)d_out;

    int n = in_sizes[0] / 3;
    int threads = 256;
    int blocks = (n + threads - 1) / threads;
    hashmlp_kernel<<<blocks, threads>>>(dirs, grid, W1, b1, W2, b2, W3, b3, W4, b4, out, n);
}